// round 2
// baseline (speedup 1.0000x reference)
#include <cuda_runtime.h>
#include <cstdint>

#define B_    8
#define N_    50000
#define CIN_  32
#define L_    9
#define K_    288        // L_*CIN_
#define CO_   64
#define M_    12500
#define NNZ_  37500

// dynamic smem layout: weight[K_*CO_] | bias[CO_] | per-warp g[K_*4] x 8 warps
#define NWARPS_PER_BLOCK 8
#define SMEM_FLOATS (K_*CO_ + CO_ + NWARPS_PER_BLOCK*K_*4)
#define SMEM_BYTES  (SMEM_FLOATS * 4)

__device__ int g_idx64_flag;

// Zero the output (poisoned 0xAA by harness) and detect index dtype width.
// jax declares int64 but silently emits int32 when x64 is disabled; if the
// data really is int64, every 8-byte word is a value in [0, N). If it is
// int32, the high 32 bits of most 8-byte reads hold another random index
// (nonzero with prob 1 - 1/N), making the combined value >= N.
__global__ void zero_detect_kernel(float4* __restrict__ out4, int n4,
                                   const long long* __restrict__ spiral) {
    int i = blockIdx.x * blockDim.x + threadIdx.x;
    int stride = gridDim.x * blockDim.x;
    float4 z = make_float4(0.f, 0.f, 0.f, 0.f);
    for (int j = i; j < n4; j += stride) out4[j] = z;
    if (blockIdx.x == 0 && threadIdx.x == 0) {
        int ok = 1;
        #pragma unroll 1
        for (int j = 0; j < 32; j++) {
            long long v = spiral[j];
            if (v < 0 || v >= N_) { ok = 0; break; }
        }
        g_idx64_flag = ok;
    }
}

// One warp per edge. For each edge e: n = cols[e]; gather g[k=l*32+c] =
// x[b, spiral[n,l], c] for 4 batches at a time into smem (coalesced 128B per
// (l,b)); matvec against the 288x64 weight resident in smem; bias + ELU;
// scale by values[e]; float2-atomicAdd into pooled[b, rows[e], :].
// Lane owns output columns (2*lane, 2*lane+1).
__global__ __launch_bounds__(256, 2)
void spiral_edge_kernel(const float*  __restrict__ x,
                        const float*  __restrict__ weight,
                        const float*  __restrict__ bias,
                        const float*  __restrict__ values,
                        const void*   __restrict__ spiral,
                        const void*   __restrict__ rows,
                        const void*   __restrict__ cols,
                        float*        __restrict__ out)
{
    extern __shared__ float smem[];
    float* wsm = smem;                 // K_*CO_ floats, original [k][o] layout
    float* bsm = smem + K_ * CO_;      // CO_ floats
    float* gsm = bsm + CO_;            // NWARPS * K_*4 floats

    const int tid = threadIdx.x;

    // cooperative weight + bias load (18432 + 64 floats)
    {
        const float4* w4 = (const float4*)weight;
        float4* ws4 = (float4*)wsm;
        for (int j = tid; j < (K_ * CO_) / 4; j += blockDim.x) ws4[j] = w4[j];
        if (tid < CO_) bsm[tid] = bias[tid];
    }
    __syncthreads();

    const int f64 = g_idx64_flag;
    const long long* s64 = (const long long*)spiral;
    const int*       s32 = (const int*)spiral;
    const long long* r64 = (const long long*)rows;
    const int*       r32 = (const int*)rows;
    const long long* c64 = (const long long*)cols;
    const int*       c32 = (const int*)cols;

    const int lane   = tid & 31;
    const int wlocal = tid >> 5;
    float* gw = gsm + wlocal * (K_ * 4);

    const int gwarp  = (blockIdx.x * blockDim.x + tid) >> 5;
    const int nwarps = (gridDim.x * blockDim.x) >> 5;

    const float2 bp = *(const float2*)(bsm + lane * 2);
    const float* wp = wsm + lane * 2;

    for (int e = gwarp; e < NNZ_; e += nwarps) {
        int n, r;
        if (f64) { n = (int)c64[e]; r = (int)r64[e]; }
        else     { n = c32[e];      r = r32[e];      }
        const float v = values[e];

        int idx[L_];
        if (f64) {
            #pragma unroll
            for (int l = 0; l < L_; l++) idx[l] = (int)s64[(long long)n * L_ + l];
        } else {
            #pragma unroll
            for (int l = 0; l < L_; l++) idx[l] = s32[n * L_ + l];
        }

        #pragma unroll
        for (int bg = 0; bg < B_; bg += 4) {
            __syncwarp();
            // gather: g[k=l*32+lane][b] for b in bg..bg+3
            #pragma unroll
            for (int l = 0; l < L_; l++) {
                #pragma unroll
                for (int b = 0; b < 4; b++) {
                    gw[(l * 32 + lane) * 4 + b] =
                        x[((bg + b) * N_ + idx[l]) * CIN_ + lane];
                }
            }
            __syncwarp();

            float2 a0 = bp, a1 = bp, a2 = bp, a3 = bp;
            #pragma unroll 4
            for (int k = 0; k < K_; k++) {
                const float4 g4 = *(const float4*)(gw + k * 4);       // broadcast
                const float2 w2 = *(const float2*)(wp + k * CO_);     // per-lane pair
                a0.x = fmaf(g4.x, w2.x, a0.x); a0.y = fmaf(g4.x, w2.y, a0.y);
                a1.x = fmaf(g4.y, w2.x, a1.x); a1.y = fmaf(g4.y, w2.y, a1.y);
                a2.x = fmaf(g4.z, w2.x, a2.x); a2.y = fmaf(g4.z, w2.y, a2.y);
                a3.x = fmaf(g4.w, w2.x, a3.x); a3.y = fmaf(g4.w, w2.y, a3.y);
            }

            float2 accs[4] = {a0, a1, a2, a3};
            #pragma unroll
            for (int b = 0; b < 4; b++) {
                float2 a = accs[b];
                a.x = (a.x > 0.f ? a.x : expm1f(a.x)) * v;
                a.y = (a.y > 0.f ? a.y : expm1f(a.y)) * v;
                atomicAdd((float2*)(out + ((bg + b) * M_ + r) * CO_ + lane * 2), a);
            }
        }
    }
}

extern "C" void kernel_launch(void* const* d_in, const int* in_sizes, int n_in,
                              void* d_out, int out_size) {
    const float* x      = (const float*)d_in[0];
    const float* weight = (const float*)d_in[1];
    const float* bias   = (const float*)d_in[2];
    const float* values = (const float*)d_in[3];
    const void*  spiral = d_in[4];
    const void*  rows   = d_in[5];
    const void*  cols   = d_in[6];
    float* out = (float*)d_out;

    zero_detect_kernel<<<512, 256>>>((float4*)out, out_size / 4,
                                     (const long long*)spiral);

    cudaFuncSetAttribute(spiral_edge_kernel,
                         cudaFuncAttributeMaxDynamicSharedMemorySize, SMEM_BYTES);
    spiral_edge_kernel<<<296, 256, SMEM_BYTES>>>(
        x, weight, bias, values, spiral, rows, cols, out);
}

// round 3
// speedup vs baseline: 1.1533x; 1.1533x over previous
#include <cuda_runtime.h>
#include <cstdint>

#define B_    8
#define N_    50000
#define CIN_  32
#define L_    9
#define K_    288        // L_*CIN_
#define CO_   64
#define M_    12500
#define NNZ_  37500

#define NWARPS 16
#define BLOCK_ (NWARPS * 32)
#define GPW    (K_ * 8)                          // floats per warp gather buffer
#define SMEM_FLOATS (K_*CO_ + CO_ + NWARPS*GPW)  // 18432 + 64 + 36864
#define SMEM_BYTES  (SMEM_FLOATS * 4)            // 221440 B

typedef unsigned long long ull;

__device__ __forceinline__ ull ffma2(ull a, ull b, ull c) {
    ull d;
    asm("fma.rn.f32x2 %0, %1, %2, %3;" : "=l"(d) : "l"(a), "l"(b), "l"(c));
    return d;
}
__device__ __forceinline__ ull pack2(float lo, float hi) {
    ull d; asm("mov.b64 %0, {%1, %2};" : "=l"(d) : "f"(lo), "f"(hi)); return d;
}
__device__ __forceinline__ float2 unpack2(ull v) {
    float2 r; asm("mov.b64 {%0, %1}, %2;" : "=f"(r.x), "=f"(r.y) : "l"(v)); return r;
}

__device__ int g_idx64_flag;

// Zero output (poisoned 0xAA) + detect index width. jax declares int64 but
// silently emits int32 when x64 is disabled; if truly int64, every 8-byte
// word of spiral is in [0, N); if int32, the high word of most 8-byte reads
// is another random index -> combined value >= N.
__global__ void zero_detect_kernel(float4* __restrict__ out4, int n4,
                                   const long long* __restrict__ spiral) {
    int i = blockIdx.x * blockDim.x + threadIdx.x;
    int stride = gridDim.x * blockDim.x;
    float4 z = make_float4(0.f, 0.f, 0.f, 0.f);
    for (int j = i; j < n4; j += stride) out4[j] = z;
    if (blockIdx.x == 0 && threadIdx.x == 0) {
        int ok = 1;
        #pragma unroll 1
        for (int j = 0; j < 32; j++) {
            long long v = spiral[j];
            if (v < 0 || v >= N_) { ok = 0; break; }
        }
        g_idx64_flag = ok;
    }
}

// One warp per edge, all 8 batches in a single k-pass.
// g stored as packed batch-pairs: gw[k*8 + 2p + {0,1}] = (g[b=2p], g[b=2p+1]).
// Lane owns output columns (2*lane, 2*lane+1). Accumulators are f32x2 over
// batch pairs: acc[p][c] = (out[b=2p][c], out[b=2p+1][c]).
__global__ __launch_bounds__(BLOCK_, 1)
void spiral_edge_kernel(const float*  __restrict__ x,
                        const float*  __restrict__ weight,
                        const float*  __restrict__ bias,
                        const float*  __restrict__ values,
                        const void*   __restrict__ spiral,
                        const void*   __restrict__ rows,
                        const void*   __restrict__ cols,
                        float*        __restrict__ out)
{
    extern __shared__ float smem[];
    float* wsm = smem;                 // K_*CO_ floats, [k][o]
    float* bsm = smem + K_ * CO_;      // CO_ floats
    float* gsm = bsm + CO_;            // NWARPS * GPW floats

    const int tid = threadIdx.x;

    // cooperative weight + bias load
    {
        const float4* w4 = (const float4*)weight;
        float4* ws4 = (float4*)wsm;
        for (int j = tid; j < (K_ * CO_) / 4; j += BLOCK_) ws4[j] = w4[j];
        if (tid < CO_) bsm[tid] = bias[tid];
    }
    __syncthreads();

    const int f64 = g_idx64_flag;
    const long long* s64 = (const long long*)spiral;
    const int*       s32 = (const int*)spiral;
    const long long* r64 = (const long long*)rows;
    const int*       r32 = (const int*)rows;
    const long long* c64 = (const long long*)cols;
    const int*       c32 = (const int*)cols;

    const int lane   = tid & 31;
    const int wlocal = tid >> 5;
    float* gw = gsm + wlocal * GPW;

    const int gwarp  = (blockIdx.x * blockDim.x + tid) >> 5;
    const int nwarps = (gridDim.x * blockDim.x) >> 5;

    const float2 bp = *(const float2*)(bsm + lane * 2);
    const ull bias0 = pack2(bp.x, bp.x);
    const ull bias1 = pack2(bp.y, bp.y);
    const float* wp = wsm + lane * 2;

    for (int e = gwarp; e < NNZ_; e += nwarps) {
        int n, r;
        if (f64) { n = (int)c64[e]; r = (int)r64[e]; }
        else     { n = c32[e];      r = r32[e];      }
        const float v = values[e];

        int idx[L_];
        if (f64) {
            #pragma unroll
            for (int l = 0; l < L_; l++) idx[l] = (int)s64[(long long)n * L_ + l];
        } else {
            #pragma unroll
            for (int l = 0; l < L_; l++) idx[l] = s32[n * L_ + l];
        }

        __syncwarp();   // previous k-pass readers done before refill
        #pragma unroll
        for (int l = 0; l < L_; l++) {
            const float* xl = x + idx[l] * CIN_ + lane;
            float g0 = xl[0 * N_ * CIN_];
            float g1 = xl[1 * N_ * CIN_];
            float g2 = xl[2 * N_ * CIN_];
            float g3 = xl[3 * N_ * CIN_];
            float g4 = xl[4 * N_ * CIN_];
            float g5 = xl[5 * N_ * CIN_];
            float g6 = xl[6 * N_ * CIN_];
            float g7 = xl[7 * N_ * CIN_];
            float* dst = gw + (l * 32 + lane) * 8;
            *(float4*)(dst)     = make_float4(g0, g1, g2, g3);
            *(float4*)(dst + 4) = make_float4(g4, g5, g6, g7);
        }
        __syncwarp();

        ull a00 = bias0, a01 = bias1;   // pair 0 (b0,b1): col0, col1
        ull a10 = bias0, a11 = bias1;   // pair 1 (b2,b3)
        ull a20 = bias0, a21 = bias1;   // pair 2 (b4,b5)
        ull a30 = bias0, a31 = bias1;   // pair 3 (b6,b7)

        #pragma unroll 4
        for (int k = 0; k < K_; k++) {
            const ulonglong2 ga = *(const ulonglong2*)(gw + k * 8);      // pairs 0,1 (broadcast)
            const ulonglong2 gb = *(const ulonglong2*)(gw + k * 8 + 4);  // pairs 2,3 (broadcast)
            const float2 w2 = *(const float2*)(wp + k * CO_);            // per-lane col pair
            const ull wxx = pack2(w2.x, w2.x);
            const ull wyy = pack2(w2.y, w2.y);
            a00 = ffma2(ga.x, wxx, a00);  a01 = ffma2(ga.x, wyy, a01);
            a10 = ffma2(ga.y, wxx, a10);  a11 = ffma2(ga.y, wyy, a11);
            a20 = ffma2(gb.x, wxx, a20);  a21 = ffma2(gb.x, wyy, a21);
            a30 = ffma2(gb.y, wxx, a30);  a31 = ffma2(gb.y, wyy, a31);
        }

        // epilogue: ELU, scale, scatter-add
        ull accs[4][2] = {{a00, a01}, {a10, a11}, {a20, a21}, {a30, a31}};
        #pragma unroll
        for (int p = 0; p < 4; p++) {
            float2 c0 = unpack2(accs[p][0]);   // col0 @ (b=2p, 2p+1)
            float2 c1 = unpack2(accs[p][1]);   // col1 @ (b=2p, 2p+1)
            float2 o0, o1;                     // per-batch (col0, col1)
            o0.x = (c0.x > 0.f ? c0.x : expm1f(c0.x)) * v;
            o0.y = (c1.x > 0.f ? c1.x : expm1f(c1.x)) * v;
            o1.x = (c0.y > 0.f ? c0.y : expm1f(c0.y)) * v;
            o1.y = (c1.y > 0.f ? c1.y : expm1f(c1.y)) * v;
            atomicAdd((float2*)(out + ((2*p + 0) * M_ + r) * CO_ + lane * 2), o0);
            atomicAdd((float2*)(out + ((2*p + 1) * M_ + r) * CO_ + lane * 2), o1);
        }
    }
}

extern "C" void kernel_launch(void* const* d_in, const int* in_sizes, int n_in,
                              void* d_out, int out_size) {
    const float* x      = (const float*)d_in[0];
    const float* weight = (const float*)d_in[1];
    const float* bias   = (const float*)d_in[2];
    const float* values = (const float*)d_in[3];
    const void*  spiral = d_in[4];
    const void*  rows   = d_in[5];
    const void*  cols   = d_in[6];
    float* out = (float*)d_out;

    zero_detect_kernel<<<512, 256>>>((float4*)out, out_size / 4,
                                     (const long long*)spiral);

    int nsm = 148;
    cudaDeviceGetAttribute(&nsm, cudaDevAttrMultiProcessorCount, 0);

    cudaFuncSetAttribute(spiral_edge_kernel,
                         cudaFuncAttributeMaxDynamicSharedMemorySize, SMEM_BYTES);
    spiral_edge_kernel<<<nsm, BLOCK_, SMEM_BYTES>>>(
        x, weight, bias, values, spiral, rows, cols, out);
}

// round 4
// speedup vs baseline: 1.2664x; 1.0982x over previous
#include <cuda_runtime.h>
#include <cstdint>

#define B_    8
#define N_    50000
#define CIN_  32
#define L_    9
#define K_    288        // L_*CIN_
#define CO_   64
#define M_    12500
#define NNZ_  37500

#define NWARPS 16
#define BLOCK_ (NWARPS * 32)
#define GPW    (K_ * 8)                          // floats per warp gather buffer
#define SMEM_FLOATS (K_*CO_ + CO_ + NWARPS*GPW)  // 18432 + 64 + 36864
#define SMEM_BYTES  (SMEM_FLOATS * 4)            // 221440 B

typedef unsigned long long ull;

__device__ __forceinline__ ull ffma2(ull a, ull b, ull c) {
    ull d;
    asm("fma.rn.f32x2 %0, %1, %2, %3;" : "=l"(d) : "l"(a), "l"(b), "l"(c));
    return d;
}
__device__ __forceinline__ ull pack2(float lo, float hi) {
    ull d; asm("mov.b64 %0, {%1, %2};" : "=l"(d) : "f"(lo), "f"(hi)); return d;
}
__device__ __forceinline__ float2 unpack2(ull v) {
    float2 r; asm("mov.b64 {%0, %1}, %2;" : "=f"(r.x), "=f"(r.y) : "l"(v)); return r;
}
__device__ __forceinline__ float elu1(float a) {
    return a > 0.f ? a : expm1f(a);
}

__device__ int g_idx64_flag;

// Zero output (poisoned 0xAA) + detect index width. jax declares int64 but
// silently emits int32 when x64 is disabled; if truly int64, every 8-byte
// word of spiral is in [0, N); if int32, the high word of most 8-byte reads
// is another random index -> combined value >= N.
__global__ void zero_detect_kernel(float4* __restrict__ out4, int n4,
                                   const long long* __restrict__ spiral) {
    int i = blockIdx.x * blockDim.x + threadIdx.x;
    int stride = gridDim.x * blockDim.x;
    float4 z = make_float4(0.f, 0.f, 0.f, 0.f);
    for (int j = i; j < n4; j += stride) out4[j] = z;
    if (blockIdx.x == 0 && threadIdx.x == 0) {
        int ok = 1;
        #pragma unroll 1
        for (int j = 0; j < 32; j++) {
            long long v = spiral[j];
            if (v < 0 || v >= N_) { ok = 0; break; }
        }
        g_idx64_flag = ok;
    }
}

// One warp per edge, all 8 batches in one k-pass.
// Gather buffer row k (32 B): [b0 b1 b2 b3 | b4 b5 b6 b7], byte offset
// 32k + 16*half, XOR-swizzled on bit4 with bit2 of k so the strided
// STS.128 fills are bank-conflict-free (reads apply the same swizzle).
// Compute partition: lanes 0-15 own batches 0-3, lanes 16-31 own batches
// 4-7; every lane owns 4 contiguous output columns 4*(lane&15).. +3.
// Per k: ONE LDS.128 for g (2 distinct 16B granules -> 1 wavefront) and
// ONE LDS.128 for weight (lane-half duplicated -> dedup to 256B, 2 wf).
__global__ __launch_bounds__(BLOCK_, 1)
void spiral_edge_kernel(const float*  __restrict__ x,
                        const float*  __restrict__ weight,
                        const float*  __restrict__ bias,
                        const float*  __restrict__ values,
                        const void*   __restrict__ spiral,
                        const void*   __restrict__ rows,
                        const void*   __restrict__ cols,
                        float*        __restrict__ out)
{
    extern __shared__ float smem[];
    float* wsm = smem;                 // K_*CO_ floats, [k][o]
    float* bsm = smem + K_ * CO_;      // CO_ floats
    float* gsm = bsm + CO_;            // NWARPS * GPW floats

    const int tid = threadIdx.x;

    // cooperative weight + bias load
    {
        const float4* w4 = (const float4*)weight;
        float4* ws4 = (float4*)wsm;
        for (int j = tid; j < (K_ * CO_) / 4; j += BLOCK_) ws4[j] = w4[j];
        if (tid < CO_) bsm[tid] = bias[tid];
    }
    __syncthreads();

    const int f64 = g_idx64_flag;
    const long long* s64 = (const long long*)spiral;
    const int*       s32 = (const int*)spiral;
    const long long* r64 = (const long long*)rows;
    const int*       r32 = (const int*)rows;
    const long long* c64 = (const long long*)cols;
    const int*       c32 = (const int*)cols;

    const int lane   = tid & 31;
    const int wlocal = tid >> 5;
    char* gw = (char*)(gsm + wlocal * GPW);

    const int gwarp  = (blockIdx.x * blockDim.x + tid) >> 5;
    const int nwarps = (gridDim.x * blockDim.x) >> 5;

    const int lane16 = lane & 15;
    const int bsel   = lane & 16;          // byte offset selecting batch half
    const int bbase  = (lane >> 4) << 2;   // 0 or 4: this lane's batch base
    const int fswz   = ((lane >> 2) & 1) << 4;  // fill swizzle (bit2 of k-row)

    // bias for this lane's 4 columns, replicated into f32x2 halves
    const float4 bv = *(const float4*)(bsm + 4 * lane16);
    const ull bc0 = pack2(bv.x, bv.x);
    const ull bc1 = pack2(bv.y, bv.y);
    const ull bc2 = pack2(bv.z, bv.z);
    const ull bc3 = pack2(bv.w, bv.w);

    const char* wlanep = (const char*)wsm + lane16 * 16;

    for (int e = gwarp; e < NNZ_; e += nwarps) {
        int n, r;
        if (f64) { n = (int)c64[e]; r = (int)r64[e]; }
        else     { n = c32[e];      r = r32[e];      }
        const float v = values[e];

        int idx[L_];
        if (f64) {
            #pragma unroll
            for (int l = 0; l < L_; l++) idx[l] = (int)s64[(long long)n * L_ + l];
        } else {
            #pragma unroll
            for (int l = 0; l < L_; l++) idx[l] = s32[n * L_ + l];
        }

        __syncwarp();   // previous k-pass readers done before refill
        #pragma unroll
        for (int l = 0; l < L_; l++) {
            const float* xl = x + idx[l] * CIN_ + lane;   // fill phase: lane = channel
            float g0 = xl[0 * N_ * CIN_];
            float g1 = xl[1 * N_ * CIN_];
            float g2 = xl[2 * N_ * CIN_];
            float g3 = xl[3 * N_ * CIN_];
            float g4 = xl[4 * N_ * CIN_];
            float g5 = xl[5 * N_ * CIN_];
            float g6 = xl[6 * N_ * CIN_];
            float g7 = xl[7 * N_ * CIN_];
            const int off = (((l * 32 + lane) << 5) ^ fswz);
            *(float4*)(gw + off)        = make_float4(g0, g1, g2, g3);
            *(float4*)(gw + (off ^ 16)) = make_float4(g4, g5, g6, g7);
        }
        __syncwarp();

        // acc[c][pair]: f32x2 over this lane's batch pair (bbase+2p, bbase+2p+1)
        ull a00 = bc0, a01 = bc0;
        ull a10 = bc1, a11 = bc1;
        ull a20 = bc2, a21 = bc2;
        ull a30 = bc3, a31 = bc3;

        #pragma unroll 8
        for (int k = 0; k < K_; k++) {
            const int swz = ((k >> 2) & 1) << 4;
            const ulonglong2 g2v =
                *(const ulonglong2*)(gw + (((k << 5) | bsel) ^ swz));
            const float4 w4 = *(const float4*)(wlanep + k * (CO_ * 4));
            const ull w0 = pack2(w4.x, w4.x);
            const ull w1 = pack2(w4.y, w4.y);
            const ull w2 = pack2(w4.z, w4.z);
            const ull w3 = pack2(w4.w, w4.w);
            a00 = ffma2(g2v.x, w0, a00);  a01 = ffma2(g2v.y, w0, a01);
            a10 = ffma2(g2v.x, w1, a10);  a11 = ffma2(g2v.y, w1, a11);
            a20 = ffma2(g2v.x, w2, a20);  a21 = ffma2(g2v.y, w2, a21);
            a30 = ffma2(g2v.x, w3, a30);  a31 = ffma2(g2v.y, w3, a31);
        }

        // epilogue: ELU, scale, float4 scatter-add (4 batches per lane)
        const float2 u00 = unpack2(a00), u01 = unpack2(a01);
        const float2 u10 = unpack2(a10), u11 = unpack2(a11);
        const float2 u20 = unpack2(a20), u21 = unpack2(a21);
        const float2 u30 = unpack2(a30), u31 = unpack2(a31);

        float* obase = out + (size_t)r * CO_ + 4 * lane16;
        {
            float4 o;
            o.x = elu1(u00.x) * v; o.y = elu1(u10.x) * v;
            o.z = elu1(u20.x) * v; o.w = elu1(u30.x) * v;
            atomicAdd((float4*)(obase + (size_t)(bbase + 0) * M_ * CO_), o);
        }
        {
            float4 o;
            o.x = elu1(u00.y) * v; o.y = elu1(u10.y) * v;
            o.z = elu1(u20.y) * v; o.w = elu1(u30.y) * v;
            atomicAdd((float4*)(obase + (size_t)(bbase + 1) * M_ * CO_), o);
        }
        {
            float4 o;
            o.x = elu1(u01.x) * v; o.y = elu1(u11.x) * v;
            o.z = elu1(u21.x) * v; o.w = elu1(u31.x) * v;
            atomicAdd((float4*)(obase + (size_t)(bbase + 2) * M_ * CO_), o);
        }
        {
            float4 o;
            o.x = elu1(u01.y) * v; o.y = elu1(u11.y) * v;
            o.z = elu1(u21.y) * v; o.w = elu1(u31.y) * v;
            atomicAdd((float4*)(obase + (size_t)(bbase + 3) * M_ * CO_), o);
        }
    }
}

extern "C" void kernel_launch(void* const* d_in, const int* in_sizes, int n_in,
                              void* d_out, int out_size) {
    const float* x      = (const float*)d_in[0];
    const float* weight = (const float*)d_in[1];
    const float* bias   = (const float*)d_in[2];
    const float* values = (const float*)d_in[3];
    const void*  spiral = d_in[4];
    const void*  rows   = d_in[5];
    const void*  cols   = d_in[6];
    float* out = (float*)d_out;

    zero_detect_kernel<<<512, 256>>>((float4*)out, out_size / 4,
                                     (const long long*)spiral);

    int nsm = 148;
    cudaDeviceGetAttribute(&nsm, cudaDevAttrMultiProcessorCount, 0);

    cudaFuncSetAttribute(spiral_edge_kernel,
                         cudaFuncAttributeMaxDynamicSharedMemorySize, SMEM_BYTES);
    spiral_edge_kernel<<<nsm, BLOCK_, SMEM_BYTES>>>(
        x, weight, bias, values, spiral, rows, cols, out);
}

// round 6
// speedup vs baseline: 1.5958x; 1.2601x over previous
#include <cuda_runtime.h>
#include <cuda_bf16.h>
#include <cstdint>

#define B_    8
#define N_    50000
#define CIN_  32
#define L_    9
#define K_    288
#define CO_   64
#define M_    12500
#define NNZ_  37500

#define GT    512                 // gemm threads per block
#define TROWS 512                 // rows per tile
#define RMAX  (NNZ_ * B_)         // worst-case compact rows (300000)

// gemm smem layout (bytes)
#define SM_B    0                 // weight [k 0..575][n 0..63] bf16, swizzled: 73728
#define SM_A    73728             // A chunk [row 0..511][128B], swizzled: 65536
#define SM_SGB  139264            // int sgb[512*9]: 18432
#define SM_BIAS 157696            // 64 floats: 256
#define SM_TOT  157952

typedef unsigned int u32;

// ---------------- device scratch ----------------
__device__ __nv_bfloat16 g_xhi[(size_t)B_ * N_ * CIN_];
__device__ __nv_bfloat16 g_xlo[(size_t)B_ * N_ * CIN_];
__device__ __nv_bfloat16 g_wh[K_ * CO_];
__device__ __nv_bfloat16 g_wl[K_ * CO_];
__device__ float         g_outc[(size_t)RMAX * CO_];   // 76.8 MB
__device__ int           g_flag[N_];
__device__ int           g_list[NNZ_];
__device__ int           g_slot[N_];
__device__ int           g_nu_d;
__device__ int           g_idx64_flag;

// ---------------- helpers ----------------
__device__ __forceinline__ u32 smem_u32(const void* p) {
    u32 a;
    asm("{ .reg .u64 t; cvta.to.shared.u64 t, %1; cvt.u32.u64 %0, t; }"
        : "=r"(a) : "l"(p));
    return a;
}
__device__ __forceinline__ void ldsm4(u32 r[4], u32 addr) {
    asm volatile("ldmatrix.sync.aligned.m8n8.x4.shared.b16 {%0,%1,%2,%3}, [%4];"
                 : "=r"(r[0]), "=r"(r[1]), "=r"(r[2]), "=r"(r[3]) : "r"(addr));
}
__device__ __forceinline__ void ldsm4t(u32 r[4], u32 addr) {
    asm volatile("ldmatrix.sync.aligned.m8n8.x4.trans.shared.b16 {%0,%1,%2,%3}, [%4];"
                 : "=r"(r[0]), "=r"(r[1]), "=r"(r[2]), "=r"(r[3]) : "r"(addr));
}
__device__ __forceinline__ void mma16816(float c[4], const u32 a[4], u32 b0, u32 b1) {
    asm volatile(
        "mma.sync.aligned.m16n8k16.row.col.f32.bf16.bf16.f32 "
        "{%0,%1,%2,%3},{%4,%5,%6,%7},{%8,%9},{%0,%1,%2,%3};"
        : "+f"(c[0]), "+f"(c[1]), "+f"(c[2]), "+f"(c[3])
        : "r"(a[0]), "r"(a[1]), "r"(a[2]), "r"(a[3]), "r"(b0), "r"(b1));
}
// A fragment address: 16B granule at [row][kb], swizzle g ^= (row&7)
__device__ __forceinline__ u32 a_addr(u32 sbA, int rowbase, int kb, int lane) {
    int lrow = rowbase + (lane & 7) + ((lane & 8) << 0) + ((lane & 8) ? 0 : 0);
    lrow = rowbase + (lane & 7) + (((lane >> 3) & 1) << 3);
    int lkb = kb + (((lane >> 4) & 1) << 4);
    return sbA + lrow * 128 + ((((lkb >> 4) ^ lrow) & 7) << 4);
}
// B fragment address (trans): k-rows, granule pair q covers n cols q*16..q*16+15
__device__ __forceinline__ u32 b_addr(u32 sbB, int krowbase, int q, int lane) {
    int lkr = krowbase + (lane & 7) + (((lane >> 3) & 1) << 3);
    int g = q * 2 + ((lane >> 4) & 1);
    return sbB + lkr * 128 + (((g ^ lkr) & 7) << 4);
}
__device__ __forceinline__ float elu1(float a) { return a > 0.f ? a : expm1f(a); }

// ============ kernel 1: zero output/flags + detect index width ============
__global__ void zero_detect_kernel(float4* __restrict__ out4, int n4,
                                   const long long* __restrict__ spiral) {
    int i = blockIdx.x * blockDim.x + threadIdx.x;
    int stride = gridDim.x * blockDim.x;
    float4 z = make_float4(0.f, 0.f, 0.f, 0.f);
    for (int j = i; j < n4; j += stride) out4[j] = z;
    for (int j = i; j < N_; j += stride) g_flag[j] = 0;
    if (blockIdx.x == 0 && threadIdx.x == 0) {
        g_nu_d = 0;
        int ok = 1;
        #pragma unroll 1
        for (int j = 0; j < 32; j++) {
            long long v = spiral[j];
            if (v < 0 || v >= N_) { ok = 0; break; }
        }
        g_idx64_flag = ok;
    }
}

// ============ kernel 2: bf16 hi/lo split of x and weight ============
__global__ void prep_kernel(const float* __restrict__ x,
                            const float* __restrict__ weight) {
    int i = blockIdx.x * blockDim.x + threadIdx.x;
    int stride = gridDim.x * blockDim.x;
    const int nx = B_ * N_ * CIN_;
    for (int j = i; j < nx; j += stride) {
        float v = x[j];
        __nv_bfloat16 h = __float2bfloat16(v);
        g_xhi[j] = h;
        g_xlo[j] = __float2bfloat16(v - __bfloat162float(h));
    }
    for (int j = i; j < K_ * CO_; j += stride) {
        float v = weight[j];
        __nv_bfloat16 h = __float2bfloat16(v);
        g_wh[j] = h;
        g_wl[j] = __float2bfloat16(v - __bfloat162float(h));
    }
}

// ============ kernel 3: build unique-col compaction ============
__global__ void compact_kernel(const void* __restrict__ cols) {
    int e = blockIdx.x * blockDim.x + threadIdx.x;
    if (e >= NNZ_) return;
    int c = g_idx64_flag ? (int)((const long long*)cols)[e]
                         : ((const int*)cols)[e];
    if (atomicExch(&g_flag[c], 1) == 0) {
        int s = atomicAdd(&g_nu_d, 1);
        g_list[s] = c;
        g_slot[c] = s;
    }
}

// ============ kernel 4: persistent gather + mma.sync GEMM + ELU ============
__global__ __launch_bounds__(GT, 1)
void gemm_kernel(const float* __restrict__ bias,
                 const void*  __restrict__ spiral) {
    extern __shared__ char smem[];
    const u32 sb  = smem_u32(smem);
    const u32 sbA = sb + SM_A;
    const u32 sbB = sb + SM_B;
    const int tid  = threadIdx.x;
    const int lane = tid & 31;
    const int wid  = tid >> 5;
    const int rowb = wid * 32;

    // weight smem fill: rows 0..287 = hi, 288..575 = lo; 16B granules swizzled
    for (int item = tid; item < 576 * 8; item += GT) {
        int g = item & 7, kr = item >> 3;
        const __nv_bfloat16* src =
            (kr < K_ ? g_wh + kr * CO_ : g_wl + (kr - K_) * CO_) + g * 8;
        uint4 v = *(const uint4*)src;
        *(uint4*)(smem + SM_B + kr * 128 + (((g ^ kr) & 7) << 4)) = v;
    }
    if (tid < CO_) ((float*)(smem + SM_BIAS))[tid] = bias[tid];
    __syncthreads();

    const int Nu = g_nu_d;
    const int R  = Nu * 8;
    const int ntiles = (R + TROWS - 1) / TROWS;
    const int f64 = g_idx64_flag;
    const long long* s64 = (const long long*)spiral;
    const int*       s32 = (const int*)spiral;
    int* sgb = (int*)(smem + SM_SGB);

    for (int tile = blockIdx.x; tile < ntiles; tile += gridDim.x) {
        __syncthreads();   // prior tile's gather/mma readers done

        // phase A: per-(row,l) gather element-offsets
        for (int item = tid; item < TROWS * L_; item += GT) {
            int row = item / L_, l = item - row * L_;
            int r = tile * TROWS + row;
            int b = r & 7;
            int n = (r < R) ? g_list[r >> 3] : g_list[0];
            int idx = f64 ? (int)s64[(size_t)n * L_ + l] : s32[n * L_ + l];
            sgb[item] = (b * N_ + idx) * CIN_;
        }

        // accumulators, bias-initialized
        float acc[2][8][4];
        #pragma unroll
        for (int nt = 0; nt < 8; nt++) {
            float2 bb = ((const float2*)(smem + SM_BIAS))[nt * 4 + (lane & 3)];
            #pragma unroll
            for (int mt = 0; mt < 2; mt++) {
                acc[mt][nt][0] = bb.x; acc[mt][nt][1] = bb.y;
                acc[mt][nt][2] = bb.x; acc[mt][nt][3] = bb.y;
            }
        }

        for (int l = 0; l < L_; l++) {
            __syncthreads();   // sgb ready (l=0) / prior mma readers done
            // gather chunk l: 4096 16B granules ([row][hi 64B | lo 64B])
            #pragma unroll
            for (int it = 0; it < 8; it++) {
                int item = tid + it * GT;
                int g = item & 7, row = item >> 3;
                int sg = sgb[row * L_ + l] + (g & 3) * 8;
                const __nv_bfloat16* src = (g < 4 ? g_xhi : g_xlo) + sg;
                uint4 v = *(const uint4*)src;
                *(uint4*)(smem + SM_A + row * 128 + (((g ^ row) & 7) << 4)) = v;
            }
            __syncthreads();

            #pragma unroll
            for (int ks = 0; ks < 2; ks++) {
                u32 Ah0[4], Ah1[4], Al0[4], Al1[4];
                ldsm4(Ah0, a_addr(sbA, rowb,      ks * 32, lane));
                ldsm4(Ah1, a_addr(sbA, rowb + 16, ks * 32, lane));
                ldsm4(Al0, a_addr(sbA, rowb,      64 + ks * 32, lane));
                ldsm4(Al1, a_addr(sbA, rowb + 16, 64 + ks * 32, lane));
                const int krh = l * 32 + ks * 16;
                #pragma unroll
                for (int q = 0; q < 4; q++) {
                    u32 bh[4], bl[4];
                    ldsm4t(bh, b_addr(sbB, krh, q, lane));
                    // hi*hi
                    mma16816(acc[0][2*q],   Ah0, bh[0], bh[1]);
                    mma16816(acc[0][2*q+1], Ah0, bh[2], bh[3]);
                    mma16816(acc[1][2*q],   Ah1, bh[0], bh[1]);
                    mma16816(acc[1][2*q+1], Ah1, bh[2], bh[3]);
                    // lo*hi
                    mma16816(acc[0][2*q],   Al0, bh[0], bh[1]);
                    mma16816(acc[0][2*q+1], Al0, bh[2], bh[3]);
                    mma16816(acc[1][2*q],   Al1, bh[0], bh[1]);
                    mma16816(acc[1][2*q+1], Al1, bh[2], bh[3]);
                    // hi*lo
                    ldsm4t(bl, b_addr(sbB, K_ + krh, q, lane));
                    mma16816(acc[0][2*q],   Ah0, bl[0], bl[1]);
                    mma16816(acc[0][2*q+1], Ah0, bl[2], bl[3]);
                    mma16816(acc[1][2*q],   Ah1, bl[0], bl[1]);
                    mma16816(acc[1][2*q+1], Ah1, bl[2], bl[3]);
                }
            }
        }

        // epilogue: ELU -> compact scratch
        #pragma unroll
        for (int mt = 0; mt < 2; mt++) {
            int row = tile * TROWS + rowb + mt * 16 + (lane >> 2);
            #pragma unroll
            for (int nt = 0; nt < 8; nt++) {
                int col = nt * 8 + (lane & 3) * 2;
                if (row < R) {
                    float2 o = make_float2(elu1(acc[mt][nt][0]),
                                           elu1(acc[mt][nt][1]));
                    *(float2*)(g_outc + (size_t)row * CO_ + col) = o;
                }
                if (row + 8 < R) {
                    float2 o = make_float2(elu1(acc[mt][nt][2]),
                                           elu1(acc[mt][nt][3]));
                    *(float2*)(g_outc + (size_t)(row + 8) * CO_ + col) = o;
                }
            }
        }
    }
}

// ============ kernel 5: edge scatter ============
__global__ void scatter_kernel(const float* __restrict__ values,
                               const void*  __restrict__ rows,
                               const void*  __restrict__ cols,
                               float*       __restrict__ out) {
    int item = blockIdx.x * blockDim.x + threadIdx.x;
    const int total = NNZ_ * B_ * 16;
    if (item >= total) return;
    int e   = item >> 7;
    int sub = item & 127;
    int b   = sub >> 4;
    int g   = sub & 15;

    int c, r;
    if (g_idx64_flag) {
        c = (int)((const long long*)cols)[e];
        r = (int)((const long long*)rows)[e];
    } else {
        c = ((const int*)cols)[e];
        r = ((const int*)rows)[e];
    }
    float v = values[e];
    int crow = g_slot[c] * 8 + b;
    const float4 d = *(const float4*)(g_outc + (size_t)crow * CO_ + g * 4);
    float4 o = make_float4(d.x * v, d.y * v, d.z * v, d.w * v);
    atomicAdd((float4*)(out + (((size_t)(b * M_ + r)) << 6) + (g << 2)), o);
}

// ============ launch ============
extern "C" void kernel_launch(void* const* d_in, const int* in_sizes, int n_in,
                              void* d_out, int out_size) {
    const float* x      = (const float*)d_in[0];
    const float* weight = (const float*)d_in[1];
    const float* bias   = (const float*)d_in[2];
    const float* values = (const float*)d_in[3];
    const void*  spiral = d_in[4];
    const void*  rows   = d_in[5];
    const void*  cols   = d_in[6];
    float* out = (float*)d_out;

    zero_detect_kernel<<<512, 256>>>((float4*)out, out_size / 4,
                                     (const long long*)spiral);
    prep_kernel<<<4096, 256>>>(x, weight);
    compact_kernel<<<(NNZ_ + 255) / 256, 256>>>(cols);

    int nsm = 148;
    cudaDeviceGetAttribute(&nsm, cudaDevAttrMultiProcessorCount, 0);

    cudaFuncSetAttribute(gemm_kernel,
                         cudaFuncAttributeMaxDynamicSharedMemorySize, SM_TOT);
    gemm_kernel<<<nsm, GT, SM_TOT>>>(bias, spiral);

    scatter_kernel<<<(NNZ_ * B_ * 16 + 255) / 256, 256>>>(values, rows, cols, out);
}

// round 9
// speedup vs baseline: 2.0655x; 1.2943x over previous
#include <cuda_runtime.h>
#include <cuda_bf16.h>
#include <cstdint>

#define B_    8
#define N_    50000
#define CIN_  32
#define L_    9
#define K_    288
#define CO_   64
#define M_    12500
#define NNZ_  37500

#define GT    512                 // gemm threads per block
#define TROWS 256                 // rows per tile
#define RMAX  (NNZ_ * B_)         // worst-case compact rows (300000)

// gemm smem layout (bytes)
#define SM_B    0                         // weight [k 0..575][64] bf16 swizzled: 73728
#define SM_A0   73728                     // A chunk buf0: 256 rows x 128B = 32768
#define SM_A1   (SM_A0 + 32768)           // 106496
#define SM_SGB  (SM_A1 + 32768)           // 139264: int sgb[256*9] = 9216
#define SM_BIAS (SM_SGB + 9216)           // 148480: 64 floats
#define SM_TOT  (SM_BIAS + 256)           // 148736

typedef unsigned int u32;

// ---------------- device scratch ----------------
__device__ __nv_bfloat16 g_xhi[(size_t)B_ * N_ * CIN_];
__device__ __nv_bfloat16 g_xlo[(size_t)B_ * N_ * CIN_];
__device__ __nv_bfloat16 g_wh[K_ * CO_];
__device__ __nv_bfloat16 g_wl[K_ * CO_];
__device__ float         g_outc[(size_t)RMAX * CO_];   // 76.8 MB
__device__ int           g_flag[N_];
__device__ int           g_list[NNZ_];
__device__ int           g_slot[N_];
__device__ int           g_nu_d;
__device__ int           g_idx64_flag;

// ---------------- helpers ----------------
__device__ __forceinline__ u32 smem_u32(const void* p) {
    u32 a;
    asm("{ .reg .u64 t; cvta.to.shared.u64 t, %1; cvt.u32.u64 %0, t; }"
        : "=r"(a) : "l"(p));
    return a;
}
__device__ __forceinline__ void cpasync16(u32 dst, const void* src) {
    asm volatile("cp.async.cg.shared.global [%0], [%1], 16;"
                 :: "r"(dst), "l"(src) : "memory");
}
__device__ __forceinline__ void cpcommit() {
    asm volatile("cp.async.commit_group;" ::: "memory");
}
__device__ __forceinline__ void cpwait0() {
    asm volatile("cp.async.wait_group 0;" ::: "memory");
}
__device__ __forceinline__ void ldsm4(u32 r[4], u32 addr) {
    asm volatile("ldmatrix.sync.aligned.m8n8.x4.shared.b16 {%0,%1,%2,%3}, [%4];"
                 : "=r"(r[0]), "=r"(r[1]), "=r"(r[2]), "=r"(r[3]) : "r"(addr));
}
__device__ __forceinline__ void ldsm4t(u32 r[4], u32 addr) {
    asm volatile("ldmatrix.sync.aligned.m8n8.x4.trans.shared.b16 {%0,%1,%2,%3}, [%4];"
                 : "=r"(r[0]), "=r"(r[1]), "=r"(r[2]), "=r"(r[3]) : "r"(addr));
}
__device__ __forceinline__ void mma16816(float c[4], const u32 a[4], u32 b0, u32 b1) {
    asm volatile(
        "mma.sync.aligned.m16n8k16.row.col.f32.bf16.bf16.f32 "
        "{%0,%1,%2,%3},{%4,%5,%6,%7},{%8,%9},{%0,%1,%2,%3};"
        : "+f"(c[0]), "+f"(c[1]), "+f"(c[2]), "+f"(c[3])
        : "r"(a[0]), "r"(a[1]), "r"(a[2]), "r"(a[3]), "r"(b0), "r"(b1));
}
// A fragment address within a 256-row buffer: 16B granule [row][kb], g ^= row&7
__device__ __forceinline__ u32 a_addr(u32 sbA, int rowbase, int kb, int lane) {
    int lrow = rowbase + (lane & 7) + (((lane >> 3) & 1) << 3);
    int lkb  = kb + (((lane >> 4) & 1) << 4);
    return sbA + lrow * 128 + ((((lkb >> 4) ^ lrow) & 7) << 4);
}
// B fragment address (trans): k-rows in SM_B, granule pair q = n cols q*16..+15
__device__ __forceinline__ u32 b_addr(u32 sbB, int krowbase, int q, int lane) {
    int lkr = krowbase + (lane & 7) + (((lane >> 3) & 1) << 3);
    int g = q * 2 + ((lane >> 4) & 1);
    return sbB + lkr * 128 + (((g ^ lkr) & 7) << 4);
}
__device__ __forceinline__ float elu1(float a) { return a > 0.f ? a : expm1f(a); }

// ============ kernel 1: zero output/flags + detect index width ============
__global__ void zero_detect_kernel(float4* __restrict__ out4, int n4,
                                   const long long* __restrict__ spiral) {
    int i = blockIdx.x * blockDim.x + threadIdx.x;
    int stride = gridDim.x * blockDim.x;
    float4 z = make_float4(0.f, 0.f, 0.f, 0.f);
    for (int j = i; j < n4; j += stride) out4[j] = z;
    for (int j = i; j < N_; j += stride) g_flag[j] = 0;
    if (blockIdx.x == 0 && threadIdx.x == 0) {
        g_nu_d = 0;
        int ok = 1;
        #pragma unroll 1
        for (int j = 0; j < 32; j++) {
            long long v = spiral[j];
            if (v < 0 || v >= N_) { ok = 0; break; }
        }
        g_idx64_flag = ok;
    }
}

// ============ kernel 2: bf16 hi/lo split of x and weight ============
__global__ void prep_kernel(const float* __restrict__ x,
                            const float* __restrict__ weight) {
    int i = blockIdx.x * blockDim.x + threadIdx.x;
    int stride = gridDim.x * blockDim.x;
    const int nx = B_ * N_ * CIN_;
    for (int j = i; j < nx; j += stride) {
        float v = x[j];
        __nv_bfloat16 h = __float2bfloat16(v);
        g_xhi[j] = h;
        g_xlo[j] = __float2bfloat16(v - __bfloat162float(h));
    }
    for (int j = i; j < K_ * CO_; j += stride) {
        float v = weight[j];
        __nv_bfloat16 h = __float2bfloat16(v);
        g_wh[j] = h;
        g_wl[j] = __float2bfloat16(v - __bfloat162float(h));
    }
}

// ============ kernel 3: build unique-col compaction ============
__global__ void compact_kernel(const void* __restrict__ cols) {
    int e = blockIdx.x * blockDim.x + threadIdx.x;
    if (e >= NNZ_) return;
    int c = g_idx64_flag ? (int)((const long long*)cols)[e]
                         : ((const int*)cols)[e];
    if (atomicExch(&g_flag[c], 1) == 0) {
        int s = atomicAdd(&g_nu_d, 1);
        g_list[s] = c;
        g_slot[c] = s;
    }
}

// ============ kernel 4: persistent pipelined gather + mma.sync GEMM ========
__global__ __launch_bounds__(GT, 1)
void gemm_kernel(const float* __restrict__ bias,
                 const void*  __restrict__ spiral) {
    extern __shared__ char smem[];
    const u32 sb  = smem_u32(smem);
    const u32 sbB = sb + SM_B;
    const int tid  = threadIdx.x;
    const int lane = tid & 31;
    const int wid  = tid >> 5;
    const int rowb = wid * 16;          // 16 rows per warp

    // weight smem fill: k-rows 0..287 = hi, 288..575 = lo; swizzled granules
    for (int item = tid; item < 576 * 8; item += GT) {
        int g = item & 7, kr = item >> 3;
        const __nv_bfloat16* src =
            (kr < K_ ? g_wh + kr * CO_ : g_wl + (kr - K_) * CO_) + g * 8;
        uint4 v = *(const uint4*)src;
        *(uint4*)(smem + SM_B + kr * 128 + (((g ^ kr) & 7) << 4)) = v;
    }
    if (tid < CO_) ((float*)(smem + SM_BIAS))[tid] = bias[tid];
    __syncthreads();

    const int Nu = g_nu_d;
    const int R  = Nu * 8;
    const int ntiles = (R + TROWS - 1) / TROWS;
    const int f64 = g_idx64_flag;
    const long long* s64 = (const long long*)spiral;
    const int*       s32 = (const int*)spiral;
    int* sgb = (int*)(smem + SM_SGB);

    // per-thread cp.async item decomposition: 2048 granules / 512 threads = 4
    // item = tid + it*GT laid out as [row 0..255][g 0..7], g fastest
    int c_g[4], c_row[4];
    #pragma unroll
    for (int it = 0; it < 4; it++) {
        int item = tid + it * GT;
        c_g[it]   = item & 7;
        c_row[it] = item >> 3;
    }

    for (int tile = blockIdx.x; tile < ntiles; tile += gridDim.x) {
        __syncthreads();   // prior tile fully drained (mma + epilogue)

        // phase A: per-(row,l) gather element offsets
        for (int item = tid; item < TROWS * L_; item += GT) {
            int row = item / L_, l = item - row * L_;
            int r = tile * TROWS + row;
            int b = r & 7;
            int n = (r < R) ? g_list[r >> 3] : g_list[0];
            int idx = f64 ? (int)s64[(size_t)n * L_ + l] : s32[n * L_ + l];
            sgb[item] = (b * N_ + idx) * CIN_;
        }
        __syncthreads();   // sgb ready

        // prologue: async-load chunk 0 into buf0
        #pragma unroll
        for (int it = 0; it < 4; it++) {
            int g = c_g[it], row = c_row[it];
            int sg = sgb[row * L_ + 0] + (g & 3) * 8;
            const __nv_bfloat16* src = (g < 4 ? g_xhi : g_xlo) + sg;
            cpasync16(sb + SM_A0 + row * 128 + (((g ^ row) & 7) << 4), src);
        }
        cpcommit();

        // accumulators, bias-initialized
        float acc[8][4];
        #pragma unroll
        for (int nt = 0; nt < 8; nt++) {
            float2 bb = ((const float2*)(smem + SM_BIAS))[nt * 4 + (lane & 3)];
            acc[nt][0] = bb.x; acc[nt][1] = bb.y;
            acc[nt][2] = bb.x; acc[nt][3] = bb.y;
        }

        #pragma unroll 1
        for (int l = 0; l < L_; l++) {
            cpwait0();          // chunk l landed (this thread's groups)
            __syncthreads();    // all threads: chunk l visible, mma l-1 drained

            // issue chunk l+1 into the other buffer
            if (l < L_ - 1) {
                const u32 dstb = sb + ((l & 1) ? SM_A0 : SM_A1);
                #pragma unroll
                for (int it = 0; it < 4; it++) {
                    int g = c_g[it], row = c_row[it];
                    int sg = sgb[row * L_ + l + 1] + (g & 3) * 8;
                    const __nv_bfloat16* src = (g < 4 ? g_xhi : g_xlo) + sg;
                    cpasync16(dstb + row * 128 + (((g ^ row) & 7) << 4), src);
                }
            }
            cpcommit();

            // MMA on chunk l
            const u32 sbA = sb + ((l & 1) ? SM_A1 : SM_A0);
            const int krh = l * 32;
            #pragma unroll
            for (int ks = 0; ks < 2; ks++) {
                u32 Ah[4], Al[4];
                ldsm4(Ah, a_addr(sbA, rowb, ks * 32, lane));
                ldsm4(Al, a_addr(sbA, rowb, 64 + ks * 32, lane));
                #pragma unroll
                for (int q = 0; q < 4; q++) {
                    u32 bh[4], bl[4];
                    ldsm4t(bh, b_addr(sbB, krh + ks * 16, q, lane));
                    mma16816(acc[2*q],   Ah, bh[0], bh[1]);
                    mma16816(acc[2*q+1], Ah, bh[2], bh[3]);
                    mma16816(acc[2*q],   Al, bh[0], bh[1]);
                    mma16816(acc[2*q+1], Al, bh[2], bh[3]);
                    ldsm4t(bl, b_addr(sbB, K_ + krh + ks * 16, q, lane));
                    mma16816(acc[2*q],   Ah, bl[0], bl[1]);
                    mma16816(acc[2*q+1], Ah, bl[2], bl[3]);
                }
            }
        }

        // epilogue: ELU -> compact scratch (registers only, no smem)
        {
            int row = tile * TROWS + rowb + (lane >> 2);
            #pragma unroll
            for (int nt = 0; nt < 8; nt++) {
                int col = nt * 8 + (lane & 3) * 2;
                if (row < R) {
                    float2 o = make_float2(elu1(acc[nt][0]), elu1(acc[nt][1]));
                    *(float2*)(g_outc + (size_t)row * CO_ + col) = o;
                }
                if (row + 8 < R) {
                    float2 o = make_float2(elu1(acc[nt][2]), elu1(acc[nt][3]));
                    *(float2*)(g_outc + (size_t)(row + 8) * CO_ + col) = o;
                }
            }
        }
    }
}

// ============ kernel 5: edge scatter ============
__global__ void scatter_kernel(const float* __restrict__ values,
                               const void*  __restrict__ rows,
                               const void*  __restrict__ cols,
                               float*       __restrict__ out) {
    int item = blockIdx.x * blockDim.x + threadIdx.x;
    const int total = NNZ_ * B_ * 16;
    if (item >= total) return;
    int e   = item >> 7;
    int sub = item & 127;
    int b   = sub >> 4;
    int g   = sub & 15;

    int c, r;
    if (g_idx64_flag) {
        c = (int)((const long long*)cols)[e];
        r = (int)((const long long*)rows)[e];
    } else {
        c = ((const int*)cols)[e];
        r = ((const int*)rows)[e];
    }
    float v = values[e];
    int crow = g_slot[c] * 8 + b;
    const float4 d = *(const float4*)(g_outc + (size_t)crow * CO_ + g * 4);
    float4 o = make_float4(d.x * v, d.y * v, d.z * v, d.w * v);
    atomicAdd((float4*)(out + (((size_t)(b * M_ + r)) << 6) + (g << 2)), o);
}

// ============ launch ============
extern "C" void kernel_launch(void* const* d_in, const int* in_sizes, int n_in,
                              void* d_out, int out_size) {
    const float* x      = (const float*)d_in[0];
    const float* weight = (const float*)d_in[1];
    const float* bias   = (const float*)d_in[2];
    const float* values = (const float*)d_in[3];
    const void*  spiral = d_in[4];
    const void*  rows   = d_in[5];
    const void*  cols   = d_in[6];
    float* out = (float*)d_out;

    zero_detect_kernel<<<512, 256>>>((float4*)out, out_size / 4,
                                     (const long long*)spiral);
    prep_kernel<<<4096, 256>>>(x, weight);
    compact_kernel<<<(NNZ_ + 255) / 256, 256>>>(cols);

    int nsm = 148;
    cudaDeviceGetAttribute(&nsm, cudaDevAttrMultiProcessorCount, 0);

    cudaFuncSetAttribute(gemm_kernel,
                         cudaFuncAttributeMaxDynamicSharedMemorySize, SM_TOT);
    gemm_kernel<<<nsm, GT, SM_TOT>>>(bias, spiral);

    scatter_kernel<<<(NNZ_ * B_ * 16 + 255) / 256, 256>>>(values, rows, cols, out);
}

// round 11
// speedup vs baseline: 2.1260x; 1.0293x over previous
#include <cuda_runtime.h>
#include <cuda_bf16.h>
#include <cstdint>

#define B_    8
#define N_    50000
#define CIN_  32
#define L_    9
#define K_    288
#define CO_   64
#define M_    12500
#define NNZ_  37500

#define GT    512                 // gemm threads per block
#define TROWS 256                 // rows per tile
#define RMAX  (NNZ_ * B_)         // worst-case compact rows (300000)

// gemm smem layout (bytes)
#define SM_B    0                         // weight [k 0..575][64] bf16 swizzled: 73728
#define SM_A0   73728                     // 4 A buffers x 32768 = 131072
#define SM_SGB  (SM_A0 + 4*32768)         // 204800: 2 x int sgb[256*9] = 18432
#define SM_BIAS (SM_SGB + 18432)          // 223232: 64 floats
#define SM_TOT  (SM_BIAS + 256)           // 223488

typedef unsigned int u32;

// ---------------- device scratch ----------------
__device__ __nv_bfloat16 g_xhi[(size_t)B_ * N_ * CIN_];
__device__ __nv_bfloat16 g_xlo[(size_t)B_ * N_ * CIN_];
__device__ __nv_bfloat16 g_wh[K_ * CO_];
__device__ __nv_bfloat16 g_wl[K_ * CO_];
__device__ float         g_outc[(size_t)RMAX * CO_];   // 76.8 MB
__device__ int           g_flag[N_];
__device__ int           g_list[NNZ_];
__device__ int           g_slot[N_];
__device__ int           g_nu_d;
__device__ int           g_idx64_flag;

// ---------------- helpers ----------------
__device__ __forceinline__ u32 smem_u32(const void* p) {
    u32 a;
    asm("{ .reg .u64 t; cvta.to.shared.u64 t, %1; cvt.u32.u64 %0, t; }"
        : "=r"(a) : "l"(p));
    return a;
}
__device__ __forceinline__ void cpasync16(u32 dst, const void* src) {
    asm volatile("cp.async.cg.shared.global [%0], [%1], 16;"
                 :: "r"(dst), "l"(src) : "memory");
}
__device__ __forceinline__ void cpcommit() {
    asm volatile("cp.async.commit_group;" ::: "memory");
}
__device__ __forceinline__ void cpwait2() {
    asm volatile("cp.async.wait_group 2;" ::: "memory");
}
__device__ __forceinline__ void ldsm4(u32 r[4], u32 addr) {
    asm volatile("ldmatrix.sync.aligned.m8n8.x4.shared.b16 {%0,%1,%2,%3}, [%4];"
                 : "=r"(r[0]), "=r"(r[1]), "=r"(r[2]), "=r"(r[3]) : "r"(addr));
}
__device__ __forceinline__ void ldsm4t(u32 r[4], u32 addr) {
    asm volatile("ldmatrix.sync.aligned.m8n8.x4.trans.shared.b16 {%0,%1,%2,%3}, [%4];"
                 : "=r"(r[0]), "=r"(r[1]), "=r"(r[2]), "=r"(r[3]) : "r"(addr));
}
__device__ __forceinline__ void mma16816(float c[4], const u32 a[4], u32 b0, u32 b1) {
    asm volatile(
        "mma.sync.aligned.m16n8k16.row.col.f32.bf16.bf16.f32 "
        "{%0,%1,%2,%3},{%4,%5,%6,%7},{%8,%9},{%0,%1,%2,%3};"
        : "+f"(c[0]), "+f"(c[1]), "+f"(c[2]), "+f"(c[3])
        : "r"(a[0]), "r"(a[1]), "r"(a[2]), "r"(a[3]), "r"(b0), "r"(b1));
}
// A fragment address within a 256-row buffer: 16B granule [row][kb], g ^= row&7
__device__ __forceinline__ u32 a_addr(u32 sbA, int rowbase, int kb, int lane) {
    int lrow = rowbase + (lane & 7) + (((lane >> 3) & 1) << 3);
    int lkb  = kb + (((lane >> 4) & 1) << 4);
    return sbA + lrow * 128 + ((((lkb >> 4) ^ lrow) & 7) << 4);
}
// B fragment address (trans): k-rows in SM_B, granule pair q = n cols q*16..+15
__device__ __forceinline__ u32 b_addr(u32 sbB, int krowbase, int q, int lane) {
    int lkr = krowbase + (lane & 7) + (((lane >> 3) & 1) << 3);
    int g = q * 2 + ((lane >> 4) & 1);
    return sbB + lkr * 128 + (((g ^ lkr) & 7) << 4);
}
__device__ __forceinline__ float elu1(float a) { return a > 0.f ? a : expm1f(a); }

// ============ kernel 1: zero output/flags + detect index width ============
__global__ void zero_detect_kernel(float4* __restrict__ out4, int n4,
                                   const long long* __restrict__ spiral) {
    int i = blockIdx.x * blockDim.x + threadIdx.x;
    int stride = gridDim.x * blockDim.x;
    float4 z = make_float4(0.f, 0.f, 0.f, 0.f);
    for (int j = i; j < n4; j += stride) out4[j] = z;
    for (int j = i; j < N_; j += stride) g_flag[j] = 0;
    if (blockIdx.x == 0 && threadIdx.x == 0) {
        g_nu_d = 0;
        int ok = 1;
        #pragma unroll 1
        for (int j = 0; j < 32; j++) {
            long long v = spiral[j];
            if (v < 0 || v >= N_) { ok = 0; break; }
        }
        g_idx64_flag = ok;
    }
}

// ============ kernel 2: bf16 hi/lo split of x and weight (vectorized) ======
__global__ void prep_kernel(const float* __restrict__ x,
                            const float* __restrict__ weight) {
    int i = blockIdx.x * blockDim.x + threadIdx.x;
    int stride = gridDim.x * blockDim.x;
    const int nx4 = (B_ * N_ * CIN_) / 4;
    for (int j = i; j < nx4; j += stride) {
        float4 v = ((const float4*)x)[j];
        __nv_bfloat16 h0 = __float2bfloat16(v.x), h1 = __float2bfloat16(v.y);
        __nv_bfloat16 h2 = __float2bfloat16(v.z), h3 = __float2bfloat16(v.w);
        __nv_bfloat162 hi01 = __nv_bfloat162(h0, h1), hi23 = __nv_bfloat162(h2, h3);
        __nv_bfloat162 lo01 = __nv_bfloat162(
            __float2bfloat16(v.x - __bfloat162float(h0)),
            __float2bfloat16(v.y - __bfloat162float(h1)));
        __nv_bfloat162 lo23 = __nv_bfloat162(
            __float2bfloat16(v.z - __bfloat162float(h2)),
            __float2bfloat16(v.w - __bfloat162float(h3)));
        ((uint2*)g_xhi)[j] = make_uint2(*(u32*)&hi01, *(u32*)&hi23);
        ((uint2*)g_xlo)[j] = make_uint2(*(u32*)&lo01, *(u32*)&lo23);
    }
    for (int j = i; j < K_ * CO_; j += stride) {
        float v = weight[j];
        __nv_bfloat16 h = __float2bfloat16(v);
        g_wh[j] = h;
        g_wl[j] = __float2bfloat16(v - __bfloat162float(h));
    }
}

// ============ kernel 3: build unique-col compaction ============
__global__ void compact_kernel(const void* __restrict__ cols) {
    int e = blockIdx.x * blockDim.x + threadIdx.x;
    if (e >= NNZ_) return;
    int c = g_idx64_flag ? (int)((const long long*)cols)[e]
                         : ((const int*)cols)[e];
    if (atomicExch(&g_flag[c], 1) == 0) {
        int s = atomicAdd(&g_nu_d, 1);
        g_list[s] = c;
        g_slot[c] = s;
    }
}

// ============ kernel 4: persistent deep-pipelined gather + mma GEMM ========
__global__ __launch_bounds__(GT, 1)
void gemm_kernel(const float* __restrict__ bias,
                 const void*  __restrict__ spiral) {
    extern __shared__ char smem[];
    const u32 sb  = smem_u32(smem);
    const u32 sbB = sb + SM_B;
    const int tid  = threadIdx.x;
    const int lane = tid & 31;
    const int wid  = tid >> 5;
    const int rowb = wid * 16;

    // weight smem fill: k-rows 0..287 = hi, 288..575 = lo; swizzled granules
    for (int item = tid; item < 576 * 8; item += GT) {
        int g = item & 7, kr = item >> 3;
        const __nv_bfloat16* src =
            (kr < K_ ? g_wh + kr * CO_ : g_wl + (kr - K_) * CO_) + g * 8;
        uint4 v = *(const uint4*)src;
        *(uint4*)(smem + SM_B + kr * 128 + (((g ^ kr) & 7) << 4)) = v;
    }
    if (tid < CO_) ((float*)(smem + SM_BIAS))[tid] = bias[tid];
    __syncthreads();

    const int Nu = g_nu_d;
    const int R  = Nu * 8;
    const int ntiles = (R + TROWS - 1) / TROWS;
    const int bid  = blockIdx.x;
    const int grid = gridDim.x;
    const int myntiles = (ntiles > bid) ? (ntiles - bid + grid - 1) / grid : 0;
    const int f64 = g_idx64_flag;
    const long long* s64 = (const long long*)spiral;
    const int*       s32 = (const int*)spiral;
    int* sgb = (int*)(smem + SM_SGB);        // two buffers of TROWS*L_

    if (myntiles == 0) return;

    // per-thread cp.async decomposition: 2048 granules / 512 threads = 4
    int c_g[4], c_row[4];
    #pragma unroll
    for (int it = 0; it < 4; it++) {
        int item = tid + it * GT;
        c_g[it]   = item & 7;
        c_row[it] = item >> 3;
    }

    // compute sgb for CTA-local tile tl into buffer (tl&1)
    auto compute_sgb = [&](int tl) {
        if (tl >= myntiles) return;
        const int tile = bid + tl * grid;
        int* sg = sgb + (tl & 1) * (TROWS * L_);
        for (int item = tid; item < TROWS * L_; item += GT) {
            int row = item / L_, l = item - row * L_;
            int r = tile * TROWS + row;
            int b = r & 7;
            int n = (r < R) ? g_list[r >> 3] : g_list[0];
            int idx = f64 ? (int)s64[(size_t)n * L_ + l] : s32[n * L_ + l];
            sg[item] = (b * N_ + idx) * CIN_;
        }
    };

    // issue chunk c (global per-CTA chunk id) into A buffer (c&3); always commit
    auto issue_chunk = [&](int c) {
        int tl = c / L_;
        int ll = c - tl * L_;
        if (tl < myntiles) {
            const int* sg = sgb + (tl & 1) * (TROWS * L_);
            const u32 dstb = sb + SM_A0 + ((c & 3) << 15);
            #pragma unroll
            for (int it = 0; it < 4; it++) {
                int g = c_g[it], row = c_row[it];
                int s = sg[row * L_ + ll] + (g & 3) * 8;
                const __nv_bfloat16* src = (g < 4 ? g_xhi : g_xlo) + s;
                cpasync16(dstb + row * 128 + (((g ^ row) & 7) << 4), src);
            }
        }
        cpcommit();
    };

    compute_sgb(0);
    __syncthreads();
    issue_chunk(0);
    issue_chunk(1);
    issue_chunk(2);

    int gci = 0;
    for (int tl = 0; tl < myntiles; tl++) {
        // accumulators, bias-initialized
        float acc[8][4];
        #pragma unroll
        for (int nt = 0; nt < 8; nt++) {
            float2 bb = ((const float2*)(smem + SM_BIAS))[nt * 4 + (lane & 3)];
            acc[nt][0] = bb.x; acc[nt][1] = bb.y;
            acc[nt][2] = bb.x; acc[nt][3] = bb.y;
        }

        #pragma unroll 1
        for (int l = 0; l < L_; l++, gci++) {
            cpwait2();          // chunk gci resident (<=2 newer groups pending)
            __syncthreads();    // visible to all; buffer (gci+3)&3 drained

            if (l == 0) compute_sgb(tl + 1);   // visible by l>=1 barriers
            issue_chunk(gci + 3);

            // MMA on chunk gci, buffer gci&3
            const u32 sbA = sb + SM_A0 + ((gci & 3) << 15);
            const int krh = l * 32;
            #pragma unroll
            for (int ks = 0; ks < 2; ks++) {
                u32 Ah[4], Al[4];
                ldsm4(Ah, a_addr(sbA, rowb, ks * 32, lane));
                ldsm4(Al, a_addr(sbA, rowb, 64 + ks * 32, lane));
                #pragma unroll
                for (int q = 0; q < 4; q++) {
                    u32 bh[4], bl[4];
                    ldsm4t(bh, b_addr(sbB, krh + ks * 16, q, lane));
                    mma16816(acc[2*q],   Ah, bh[0], bh[1]);
                    mma16816(acc[2*q+1], Ah, bh[2], bh[3]);
                    mma16816(acc[2*q],   Al, bh[0], bh[1]);
                    mma16816(acc[2*q+1], Al, bh[2], bh[3]);
                    ldsm4t(bl, b_addr(sbB, K_ + krh + ks * 16, q, lane));
                    mma16816(acc[2*q],   Ah, bl[0], bl[1]);
                    mma16816(acc[2*q+1], Ah, bl[2], bl[3]);
                }
            }
        }

        // epilogue: ELU -> compact scratch (overlaps in-flight next-tile loads)
        {
            const int tile = bid + tl * grid;
            int row = tile * TROWS + rowb + (lane >> 2);
            #pragma unroll
            for (int nt = 0; nt < 8; nt++) {
                int col = nt * 8 + (lane & 3) * 2;
                if (row < R) {
                    float2 o = make_float2(elu1(acc[nt][0]), elu1(acc[nt][1]));
                    *(float2*)(g_outc + (size_t)row * CO_ + col) = o;
                }
                if (row + 8 < R) {
                    float2 o = make_float2(elu1(acc[nt][2]), elu1(acc[nt][3]));
                    *(float2*)(g_outc + (size_t)(row + 8) * CO_ + col) = o;
                }
            }
        }
    }
}

// ============ kernel 5: edge scatter ============
__global__ void scatter_kernel(const float* __restrict__ values,
                               const void*  __restrict__ rows,
                               const void*  __restrict__ cols,
                               float*       __restrict__ out) {
    int item = blockIdx.x * blockDim.x + threadIdx.x;
    const int total = NNZ_ * B_ * 16;
    if (item >= total) return;
    int e   = item >> 7;
    int sub = item & 127;
    int b   = sub >> 4;
    int g   = sub & 15;

    int c, r;
    if (g_idx64_flag) {
        c = (int)((const long long*)cols)[e];
        r = (int)((const long long*)rows)[e];
    } else {
        c = ((const int*)cols)[e];
        r = ((const int*)rows)[e];
    }
    float v = values[e];
    int crow = g_slot[c] * 8 + b;
    const float4 d = *(const float4*)(g_outc + (size_t)crow * CO_ + g * 4);
    float4 o = make_float4(d.x * v, d.y * v, d.z * v, d.w * v);
    atomicAdd((float4*)(out + (((size_t)(b * M_ + r)) << 6) + (g << 2)), o);
}

// ============ launch ============
extern "C" void kernel_launch(void* const* d_in, const int* in_sizes, int n_in,
                              void* d_out, int out_size) {
    const float* x      = (const float*)d_in[0];
    const float* weight = (const float*)d_in[1];
    const float* bias   = (const float*)d_in[2];
    const float* values = (const float*)d_in[3];
    const void*  spiral = d_in[4];
    const void*  rows   = d_in[5];
    const void*  cols   = d_in[6];
    float* out = (float*)d_out;

    zero_detect_kernel<<<512, 256>>>((float4*)out, out_size / 4,
                                     (const long long*)spiral);
    prep_kernel<<<4096, 256>>>(x, weight);
    compact_kernel<<<(NNZ_ + 255) / 256, 256>>>(cols);

    int nsm = 148;
    cudaDeviceGetAttribute(&nsm, cudaDevAttrMultiProcessorCount, 0);

    cudaFuncSetAttribute(gemm_kernel,
                         cudaFuncAttributeMaxDynamicSharedMemorySize, SM_TOT);
    gemm_kernel<<<nsm, GT, SM_TOT>>>(bias, spiral);

    scatter_kernel<<<(NNZ_ * B_ * 16 + 255) / 256, 256>>>(values, rows, cols, out);
}

// round 12
// speedup vs baseline: 2.4483x; 1.1516x over previous
#include <cuda_runtime.h>
#include <cuda_bf16.h>
#include <cstdint>

#define B_    8
#define N_    50000
#define CIN_  32
#define L_    9
#define K_    288
#define CO_   64
#define M_    12500
#define NNZ_  37500

#define GT    512                 // gemm threads per block
#define TROWS 256                 // rows per tile
#define WROWS 16                  // rows per warp
#define RMAX  (NNZ_ * B_)         // worst-case compact rows (300000)

// gemm smem layout (bytes)
#define SM_B    0                         // weight [k 0..575][64] bf16 swizzled: 73728
#define SM_A0   73728                     // 4 A buffers x 32768 = 131072
#define SM_SGB  (SM_A0 + 4*32768)         // 204800: per-warp 2 x 144 ints = 18432
#define SM_BIAS (SM_SGB + 18432)          // 223232: 64 floats
#define SM_TOT  (SM_BIAS + 256)           // 223488

typedef unsigned int u32;

// ---------------- device scratch ----------------
__device__ __nv_bfloat16 g_xhi[(size_t)B_ * N_ * CIN_];
__device__ __nv_bfloat16 g_xlo[(size_t)B_ * N_ * CIN_];
__device__ __nv_bfloat16 g_wh[K_ * CO_];
__device__ __nv_bfloat16 g_wl[K_ * CO_];
__device__ float         g_outc[(size_t)RMAX * CO_];   // 76.8 MB
__device__ int           g_flag[N_];
__device__ int           g_list[NNZ_];
__device__ int           g_slot[N_];
__device__ int           g_nu_d;
__device__ int           g_idx64_flag;

// ---------------- helpers ----------------
__device__ __forceinline__ u32 smem_u32(const void* p) {
    u32 a;
    asm("{ .reg .u64 t; cvta.to.shared.u64 t, %1; cvt.u32.u64 %0, t; }"
        : "=r"(a) : "l"(p));
    return a;
}
__device__ __forceinline__ void cpasync16(u32 dst, const void* src) {
    asm volatile("cp.async.cg.shared.global [%0], [%1], 16;"
                 :: "r"(dst), "l"(src) : "memory");
}
__device__ __forceinline__ void cpcommit() {
    asm volatile("cp.async.commit_group;" ::: "memory");
}
__device__ __forceinline__ void cpwait2() {
    asm volatile("cp.async.wait_group 2;" ::: "memory");
}
__device__ __forceinline__ void ldsm4(u32 r[4], u32 addr) {
    asm volatile("ldmatrix.sync.aligned.m8n8.x4.shared.b16 {%0,%1,%2,%3}, [%4];"
                 : "=r"(r[0]), "=r"(r[1]), "=r"(r[2]), "=r"(r[3]) : "r"(addr));
}
__device__ __forceinline__ void ldsm4t(u32 r[4], u32 addr) {
    asm volatile("ldmatrix.sync.aligned.m8n8.x4.trans.shared.b16 {%0,%1,%2,%3}, [%4];"
                 : "=r"(r[0]), "=r"(r[1]), "=r"(r[2]), "=r"(r[3]) : "r"(addr));
}
__device__ __forceinline__ void mma16816(float c[4], const u32 a[4], u32 b0, u32 b1) {
    asm volatile(
        "mma.sync.aligned.m16n8k16.row.col.f32.bf16.bf16.f32 "
        "{%0,%1,%2,%3},{%4,%5,%6,%7},{%8,%9},{%0,%1,%2,%3};"
        : "+f"(c[0]), "+f"(c[1]), "+f"(c[2]), "+f"(c[3])
        : "r"(a[0]), "r"(a[1]), "r"(a[2]), "r"(a[3]), "r"(b0), "r"(b1));
}
// A fragment address within a 256-row buffer: 16B granule [row][kb], g ^= row&7
__device__ __forceinline__ u32 a_addr(u32 sbA, int rowbase, int kb, int lane) {
    int lrow = rowbase + (lane & 7) + (((lane >> 3) & 1) << 3);
    int lkb  = kb + (((lane >> 4) & 1) << 4);
    return sbA + lrow * 128 + ((((lkb >> 4) ^ lrow) & 7) << 4);
}
// B fragment address (trans): k-rows in SM_B, granule pair q = n cols q*16..+15
__device__ __forceinline__ u32 b_addr(u32 sbB, int krowbase, int q, int lane) {
    int lkr = krowbase + (lane & 7) + (((lane >> 3) & 1) << 3);
    int g = q * 2 + ((lane >> 4) & 1);
    return sbB + lkr * 128 + (((g ^ lkr) & 7) << 4);
}
__device__ __forceinline__ float elu1(float a) { return a > 0.f ? a : expm1f(a); }

// ============ kernel 1: zero output/flags + detect index width ============
__global__ void zero_detect_kernel(float4* __restrict__ out4, int n4,
                                   const long long* __restrict__ spiral) {
    int i = blockIdx.x * blockDim.x + threadIdx.x;
    int stride = gridDim.x * blockDim.x;
    float4 z = make_float4(0.f, 0.f, 0.f, 0.f);
    for (int j = i; j < n4; j += stride) out4[j] = z;
    for (int j = i; j < N_; j += stride) g_flag[j] = 0;
    if (blockIdx.x == 0 && threadIdx.x == 0) {
        g_nu_d = 0;
        int ok = 1;
        #pragma unroll 1
        for (int j = 0; j < 32; j++) {
            long long v = spiral[j];
            if (v < 0 || v >= N_) { ok = 0; break; }
        }
        g_idx64_flag = ok;
    }
}

// ============ kernel 2: bf16 hi/lo split of x and weight (vectorized) ======
__global__ void prep_kernel(const float* __restrict__ x,
                            const float* __restrict__ weight) {
    int i = blockIdx.x * blockDim.x + threadIdx.x;
    int stride = gridDim.x * blockDim.x;
    const int nx4 = (B_ * N_ * CIN_) / 4;
    for (int j = i; j < nx4; j += stride) {
        float4 v = ((const float4*)x)[j];
        __nv_bfloat16 h0 = __float2bfloat16(v.x), h1 = __float2bfloat16(v.y);
        __nv_bfloat16 h2 = __float2bfloat16(v.z), h3 = __float2bfloat16(v.w);
        __nv_bfloat162 hi01 = __nv_bfloat162(h0, h1), hi23 = __nv_bfloat162(h2, h3);
        __nv_bfloat162 lo01 = __nv_bfloat162(
            __float2bfloat16(v.x - __bfloat162float(h0)),
            __float2bfloat16(v.y - __bfloat162float(h1)));
        __nv_bfloat162 lo23 = __nv_bfloat162(
            __float2bfloat16(v.z - __bfloat162float(h2)),
            __float2bfloat16(v.w - __bfloat162float(h3)));
        ((uint2*)g_xhi)[j] = make_uint2(*(u32*)&hi01, *(u32*)&hi23);
        ((uint2*)g_xlo)[j] = make_uint2(*(u32*)&lo01, *(u32*)&lo23);
    }
    for (int j = i; j < K_ * CO_; j += stride) {
        float v = weight[j];
        __nv_bfloat16 h = __float2bfloat16(v);
        g_wh[j] = h;
        g_wl[j] = __float2bfloat16(v - __bfloat162float(h));
    }
}

// ============ kernel 3: build unique-col compaction ============
__global__ void compact_kernel(const void* __restrict__ cols) {
    int e = blockIdx.x * blockDim.x + threadIdx.x;
    if (e >= NNZ_) return;
    int c = g_idx64_flag ? (int)((const long long*)cols)[e]
                         : ((const int*)cols)[e];
    if (atomicExch(&g_flag[c], 1) == 0) {
        int s = atomicAdd(&g_nu_d, 1);
        g_list[s] = c;
        g_slot[c] = s;
    }
}

// ============ kernel 4: per-warp pipelined gather + mma GEMM ===============
// After init there are NO CTA barriers: each warp gathers its own 16-row
// A-slice with cp.async, tracks its own commit groups, and free-runs.
__global__ __launch_bounds__(GT, 1)
void gemm_kernel(const float* __restrict__ bias,
                 const void*  __restrict__ spiral) {
    extern __shared__ char smem[];
    const u32 sb  = smem_u32(smem);
    const u32 sbB = sb + SM_B;
    const int tid  = threadIdx.x;
    const int lane = tid & 31;
    const int wid  = tid >> 5;
    const int rowb = wid * WROWS;

    // weight smem fill: k-rows 0..287 = hi, 288..575 = lo; swizzled granules
    for (int item = tid; item < 576 * 8; item += GT) {
        int g = item & 7, kr = item >> 3;
        const __nv_bfloat16* src =
            (kr < K_ ? g_wh + kr * CO_ : g_wl + (kr - K_) * CO_) + g * 8;
        uint4 v = *(const uint4*)src;
        *(uint4*)(smem + SM_B + kr * 128 + (((g ^ kr) & 7) << 4)) = v;
    }
    if (tid < CO_) ((float*)(smem + SM_BIAS))[tid] = bias[tid];
    __syncthreads();       // last CTA-wide barrier

    const int Nu = g_nu_d;
    const int R  = Nu * 8;
    const int ntiles = (R + TROWS - 1) / TROWS;
    const int bid  = blockIdx.x;
    const int grid = gridDim.x;
    const int myntiles = (ntiles > bid) ? (ntiles - bid + grid - 1) / grid : 0;
    const int f64 = g_idx64_flag;
    const long long* s64 = (const long long*)spiral;
    const int*       s32 = (const int*)spiral;
    // per-warp sgb: 2 buffers x (WROWS*L_) ints
    int* sgbw = (int*)(smem + SM_SGB) + wid * 2 * (WROWS * L_);

    if (myntiles == 0) return;

    // per-lane cp.async decomposition: 16 rows x 8 granules = 128 / 32 = 4
    int c_g[4], c_row[4];
    #pragma unroll
    for (int it = 0; it < 4; it++) {
        int item = lane + it * 32;       // [row][g], g fastest
        c_g[it]   = item & 7;
        c_row[it] = rowb + (item >> 3);  // absolute row in tile
    }

    // compute this warp's sgb for CTA-local tile tl into buffer (tl&1)
    auto compute_sgb = [&](int tl) {
        if (tl >= myntiles) return;
        const int tile = bid + tl * grid;
        int* sg = sgbw + (tl & 1) * (WROWS * L_);
        for (int item = lane; item < WROWS * L_; item += 32) {
            int row = item / L_, l = item - row * L_;
            int r = tile * TROWS + rowb + row;
            int b = r & 7;
            int n = (r < R) ? g_list[r >> 3] : g_list[0];
            int idx = f64 ? (int)s64[(size_t)n * L_ + l] : s32[n * L_ + l];
            sg[item] = (b * N_ + idx) * CIN_;
        }
    };

    // issue this warp's slice of chunk c into A buffer (c&3); always commit
    auto issue_chunk = [&](int c) {
        int tl = c / L_;
        int ll = c - tl * L_;
        if (tl < myntiles) {
            const int* sg = sgbw + (tl & 1) * (WROWS * L_);
            const u32 dstb = sb + SM_A0 + ((c & 3) << 15);
            #pragma unroll
            for (int it = 0; it < 4; it++) {
                int g = c_g[it], row = c_row[it];
                int s = sg[(row - rowb) * L_ + ll] + (g & 3) * 8;
                const __nv_bfloat16* src = (g < 4 ? g_xhi : g_xlo) + s;
                cpasync16(dstb + row * 128 + (((g ^ row) & 7) << 4), src);
            }
        }
        cpcommit();
    };

    compute_sgb(0);
    __syncwarp();
    issue_chunk(0);
    issue_chunk(1);
    issue_chunk(2);

    int gci = 0;
    for (int tl = 0; tl < myntiles; tl++) {
        // accumulators, bias-initialized
        float acc[8][4];
        #pragma unroll
        for (int nt = 0; nt < 8; nt++) {
            float2 bb = ((const float2*)(smem + SM_BIAS))[nt * 4 + (lane & 3)];
            acc[nt][0] = bb.x; acc[nt][1] = bb.y;
            acc[nt][2] = bb.x; acc[nt][3] = bb.y;
        }

        #pragma unroll 1
        for (int l = 0; l < L_; l++, gci++) {
            cpwait2();         // this warp's chunk gci resident
            __syncwarp();      // cross-lane visibility within the warp

            if (l == 0) { compute_sgb(tl + 1); __syncwarp(); }
            issue_chunk(gci + 3);

            // MMA on chunk gci, buffer gci&3, this warp's 16 rows
            const u32 sbA = sb + SM_A0 + ((gci & 3) << 15);
            const int krh = l * 32;
            #pragma unroll
            for (int ks = 0; ks < 2; ks++) {
                u32 Ah[4], Al[4];
                ldsm4(Ah, a_addr(sbA, rowb, ks * 32, lane));
                ldsm4(Al, a_addr(sbA, rowb, 64 + ks * 32, lane));
                #pragma unroll
                for (int q = 0; q < 4; q++) {
                    u32 bh[4], bl[4];
                    ldsm4t(bh, b_addr(sbB, krh + ks * 16, q, lane));
                    mma16816(acc[2*q],   Ah, bh[0], bh[1]);
                    mma16816(acc[2*q+1], Ah, bh[2], bh[3]);
                    mma16816(acc[2*q],   Al, bh[0], bh[1]);
                    mma16816(acc[2*q+1], Al, bh[2], bh[3]);
                    ldsm4t(bl, b_addr(sbB, K_ + krh + ks * 16, q, lane));
                    mma16816(acc[2*q],   Ah, bl[0], bl[1]);
                    mma16816(acc[2*q+1], Ah, bl[2], bl[3]);
                }
            }
        }

        // epilogue: ELU -> compact scratch (warp-private rows)
        {
            const int tile = bid + tl * grid;
            int row = tile * TROWS + rowb + (lane >> 2);
            #pragma unroll
            for (int nt = 0; nt < 8; nt++) {
                int col = nt * 8 + (lane & 3) * 2;
                if (row < R) {
                    float2 o = make_float2(elu1(acc[nt][0]), elu1(acc[nt][1]));
                    *(float2*)(g_outc + (size_t)row * CO_ + col) = o;
                }
                if (row + 8 < R) {
                    float2 o = make_float2(elu1(acc[nt][2]), elu1(acc[nt][3]));
                    *(float2*)(g_outc + (size_t)(row + 8) * CO_ + col) = o;
                }
            }
        }
    }
}

// ============ kernel 5: edge scatter ============
__global__ void scatter_kernel(const float* __restrict__ values,
                               const void*  __restrict__ rows,
                               const void*  __restrict__ cols,
                               float*       __restrict__ out) {
    int item = blockIdx.x * blockDim.x + threadIdx.x;
    const int total = NNZ_ * B_ * 16;
    if (item >= total) return;
    int e   = item >> 7;
    int sub = item & 127;
    int b   = sub >> 4;
    int g   = sub & 15;

    int c, r;
    if (g_idx64_flag) {
        c = (int)((const long long*)cols)[e];
        r = (int)((const long long*)rows)[e];
    } else {
        c = ((const int*)cols)[e];
        r = ((const int*)rows)[e];
    }
    float v = values[e];
    int crow = g_slot[c] * 8 + b;
    const float4 d = *(const float4*)(g_outc + (size_t)crow * CO_ + g * 4);
    float4 o = make_float4(d.x * v, d.y * v, d.z * v, d.w * v);
    atomicAdd((float4*)(out + (((size_t)(b * M_ + r)) << 6) + (g << 2)), o);
}

// ============ launch ============
extern "C" void kernel_launch(void* const* d_in, const int* in_sizes, int n_in,
                              void* d_out, int out_size) {
    const float* x      = (const float*)d_in[0];
    const float* weight = (const float*)d_in[1];
    const float* bias   = (const float*)d_in[2];
    const float* values = (const float*)d_in[3];
    const void*  spiral = d_in[4];
    const void*  rows   = d_in[5];
    const void*  cols   = d_in[6];
    float* out = (float*)d_out;

    zero_detect_kernel<<<512, 256>>>((float4*)out, out_size / 4,
                                     (const long long*)spiral);
    prep_kernel<<<4096, 256>>>(x, weight);
    compact_kernel<<<(NNZ_ + 255) / 256, 256>>>(cols);

    int nsm = 148;
    cudaDeviceGetAttribute(&nsm, cudaDevAttrMultiProcessorCount, 0);

    cudaFuncSetAttribute(gemm_kernel,
                         cudaFuncAttributeMaxDynamicSharedMemorySize, SM_TOT);
    gemm_kernel<<<nsm, GT, SM_TOT>>>(bias, spiral);

    scatter_kernel<<<(NNZ_ * B_ * 16 + 255) / 256, 256>>>(values, rows, cols, out);
}